// round 13
// baseline (speedup 1.0000x reference)
#include <cuda_runtime.h>
#include <cuda_bf16.h>
#include <math.h>
#include <stdint.h>

// Problem constants
#define BB 64
#define TT 1024
#define QD 1024
#define CD 512
#define SPLITS 16
#define TCHUNK (TT / SPLITS)    // 64 rows per block
#define NT 128

#define CROWS  8                               // rows per pipeline chunk
#define NCHUNK (TCHUNK / CROWS)                // 8 chunks
#define CBYTES (CROWS * CD * 4)                // 16384 bytes
#define NSLOT  2                               // double buffer

// Output layout (float32): context[B,CD] | a[B,T] | u_new[B] | sq_new[B]
#define CTX_OFF 0
#define A_OFF   (BB * CD)                 // 32768
#define U_OFF   (A_OFF + BB * TT)         // 98304
#define SQ_OFF  (U_OFF + BB)              // 98368

// Scratch
__device__ float        g_partial[BB * SPLITS * CD];
__device__ float        g_vsum[BB * SPLITS];
__device__ float        g_hdot[BB * SPLITS * 2];
__device__ unsigned int g_cnt[BB];          // zero-init; finalizer resets

__device__ __forceinline__ float alpha_v(
    const float* __restrict__ arow, int t, float ub, float sqb)
{
    const float cur  = arow[t];
    const float prev = (t > 0) ? arow[t - 1] : 0.0f;
    const float base = fmaf(-ub, cur, cur) + fmaf(ub, prev, 1e-6f);
    return __expf(sqb * __logf(base));   // base > 0 always
}

#define MBAR_INIT(mb) \
    asm volatile("mbarrier.init.shared.b64 [%0], 1;" :: "r"(mb) : "memory")

#define EXPECT_AND_COPY(mb, dst, src) do {                                        \
    asm volatile("mbarrier.arrive.expect_tx.shared.b64 _, [%0], %1;"              \
                 :: "r"(mb), "r"((unsigned)CBYTES) : "memory");                   \
    asm volatile("cp.async.bulk.shared::cta.global.mbarrier::complete_tx::bytes " \
                 "[%0], [%1], %2, [%3];"                                          \
                 :: "r"(dst), "l"(src), "r"((unsigned)CBYTES), "r"(mb)            \
                 : "memory");                                                     \
} while (0)

#define WAIT_PARITY(mb, ph) do {                                                  \
    unsigned _done = 0;                                                           \
    while (!_done) {                                                              \
        asm volatile("{\n\t.reg .pred p;\n\t"                                     \
            "mbarrier.try_wait.parity.acquire.cta.shared::cta.b64 p, [%1], %2, 0x989680;\n\t" \
            "selp.b32 %0, 1, 0, p;\n\t}"                                          \
            : "=r"(_done) : "r"(mb), "r"((unsigned)(ph)) : "memory");             \
    }                                                                             \
} while (0)

struct SM {
    alignas(128) float buf[NSLOT][CROWS * CD];  // 32 KB double buffer
    unsigned long long mbar[NSLOT];
    float sa[TCHUNK];
    float ru[4], rs[4];
    float fu[4], fs[4];
    unsigned int tk;
};

// ---------------------------------------------------------------------------
// Single kernel, t-split + TMA bulk double-buffer. Grid (SPLITS, B), 128 thr.
// Producer: tid 0 issues cp.async.bulk 16KB chunks (mbarrier complete_tx).
// Consumers: conflict-free LDS.128 + FMA from smem. Tail: last ticket block
// per batch finalizes ctx/a/heads (cheap, overlapped).
// ---------------------------------------------------------------------------
__global__ void __launch_bounds__(NT) k_all(
    const float* __restrict__ inputs,
    const float* __restrict__ alpha,
    const float* __restrict__ u,
    const float* __restrict__ sq,
    const float* __restrict__ query,
    const float* __restrict__ W_u,  const float* __restrict__ b_u,
    const float* __restrict__ W_sq, const float* __restrict__ b_sq,
    float* __restrict__ out,
    float* __restrict__ partial,
    float* __restrict__ vsum,
    float* __restrict__ hdot,
    unsigned int* __restrict__ cnt)
{
    const int s   = blockIdx.x;
    const int b   = blockIdx.y;
    const int tid = threadIdx.x;

    __shared__ SM sm;

    const float ub  = u[b];
    const float sqb = sq[b];
    const float* arow = alpha + (size_t)b * TT;

    // chunk weights
    if (tid < TCHUNK)
        sm.sa[tid] = alpha_v(arow, s * TCHUNK + tid, ub, sqb);

    const uint32_t mb0  = (uint32_t)__cvta_generic_to_shared(&sm.mbar[0]);
    const uint32_t mb1  = (uint32_t)__cvta_generic_to_shared(&sm.mbar[1]);
    const uint32_t bufu = (uint32_t)__cvta_generic_to_shared(&sm.buf[0][0]);

    if (tid == 0) { MBAR_INIT(mb0); MBAR_INIT(mb1); }
    __syncthreads();

    // chunk v-sum (warp 0, deterministic order)
    if (tid < 32) {
        float x = sm.sa[tid] + sm.sa[tid + 32];
        #pragma unroll
        for (int o = 16; o > 0; o >>= 1) x += __shfl_xor_sync(0xffffffffu, x, o);
        if (tid == 0) vsum[(size_t)b * SPLITS + s] = x;
    }

    const char* gsrc =
        (const char*)(inputs + ((size_t)b * TT + (size_t)s * TCHUNK) * CD);

    if (tid == 0) {
        EXPECT_AND_COPY(mb0, bufu,          gsrc);
        EXPECT_AND_COPY(mb1, bufu + CBYTES, gsrc + CBYTES);
    }

    float4 ac0 = {0,0,0,0}, ac1 = {0,0,0,0}, ac2 = {0,0,0,0}, ac3 = {0,0,0,0};

    #pragma unroll
    for (int c = 0; c < NCHUNK; c++) {
        const uint32_t mb = (c & 1) ? mb1 : mb0;
        WAIT_PARITY(mb, (c >> 1) & 1);

        const float4* __restrict__ slot = (const float4*)&sm.buf[c & 1][0];
        const float*  __restrict__ w    = &sm.sa[c * CROWS];

        #pragma unroll
        for (int r = 0; r < CROWS; r += 4) {
            const float4 v0 = slot[(size_t)(r + 0) * (CD/4) + tid];
            const float4 v1 = slot[(size_t)(r + 1) * (CD/4) + tid];
            const float4 v2 = slot[(size_t)(r + 2) * (CD/4) + tid];
            const float4 v3 = slot[(size_t)(r + 3) * (CD/4) + tid];
            const float w0 = w[r + 0], w1 = w[r + 1], w2 = w[r + 2], w3 = w[r + 3];
            ac0.x = fmaf(w0, v0.x, ac0.x); ac0.y = fmaf(w0, v0.y, ac0.y);
            ac0.z = fmaf(w0, v0.z, ac0.z); ac0.w = fmaf(w0, v0.w, ac0.w);
            ac1.x = fmaf(w1, v1.x, ac1.x); ac1.y = fmaf(w1, v1.y, ac1.y);
            ac1.z = fmaf(w1, v1.z, ac1.z); ac1.w = fmaf(w1, v1.w, ac1.w);
            ac2.x = fmaf(w2, v2.x, ac2.x); ac2.y = fmaf(w2, v2.y, ac2.y);
            ac2.z = fmaf(w2, v2.z, ac2.z); ac2.w = fmaf(w2, v2.w, ac2.w);
            ac3.x = fmaf(w3, v3.x, ac3.x); ac3.y = fmaf(w3, v3.y, ac3.y);
            ac3.z = fmaf(w3, v3.z, ac3.z); ac3.w = fmaf(w3, v3.w, ac3.w);
        }
        __syncthreads();   // all threads done with this slot
        if (tid == 0 && c + NSLOT < NCHUNK) {
            EXPECT_AND_COPY(mb, bufu + (unsigned)(c & 1) * CBYTES,
                            gsrc + (size_t)(c + NSLOT) * CBYTES);
        }
    }

    float4 r4;
    r4.x = (ac0.x + ac1.x) + (ac2.x + ac3.x);
    r4.y = (ac0.y + ac1.y) + (ac2.y + ac3.y);
    r4.z = (ac0.z + ac1.z) + (ac2.z + ac3.z);
    r4.w = (ac0.w + ac1.w) + (ac2.w + ac3.w);
    ((float4*)(partial + ((size_t)b * SPLITS + s) * CD))[tid] = r4;

    // head-dot partials
    const float4 wu = ((const float4*)W_u)[tid];
    const float4 ws = ((const float4*)W_sq)[tid];
    float hu = r4.x * wu.x + r4.y * wu.y + r4.z * wu.z + r4.w * wu.w;
    float hs = r4.x * ws.x + r4.y * ws.y + r4.z * ws.z + r4.w * ws.w;
    #pragma unroll
    for (int o = 16; o > 0; o >>= 1) {
        hu += __shfl_xor_sync(0xffffffffu, hu, o);
        hs += __shfl_xor_sync(0xffffffffu, hs, o);
    }
    if ((tid & 31) == 0) { sm.ru[tid >> 5] = hu; sm.rs[tid >> 5] = hs; }
    __syncthreads();

    if (tid == 0) {
        hdot[((size_t)b * SPLITS + s) * 2 + 0] =
            (sm.ru[0] + sm.ru[1]) + (sm.ru[2] + sm.ru[3]);
        hdot[((size_t)b * SPLITS + s) * 2 + 1] =
            (sm.rs[0] + sm.rs[1]) + (sm.rs[2] + sm.rs[3]);
        unsigned int old;
        asm volatile("atom.add.acq_rel.gpu.global.u32 %0, [%1], %2;"
                     : "=r"(old) : "l"(cnt + b), "r"(1u) : "memory");
        sm.tk = old;
    }
    __syncthreads();
    if (sm.tk != SPLITS - 1) return;

    // ===================== finalize batch b (last block) =====================
    if (tid == 0) cnt[b] = 0u;               // replay-safe reset

    float S = 0.0f;
    #pragma unroll
    for (int k = 0; k < SPLITS; k++) S += vsum[(size_t)b * SPLITS + k];
    const float inv = 1.0f / S;

    {   // normalized context
        const float4* __restrict__ p4 =
            (const float4*)(partial + (size_t)b * SPLITS * CD);
        float4 c4 = {0,0,0,0};
        #pragma unroll
        for (int k = 0; k < SPLITS; k++) {
            const float4 p = p4[(size_t)k * (CD/4) + tid];
            c4.x += p.x; c4.y += p.y; c4.z += p.z; c4.w += p.w;
        }
        c4.x *= inv; c4.y *= inv; c4.z *= inv; c4.w *= inv;
        ((float4*)(out + CTX_OFF + (size_t)b * CD))[tid] = c4;
    }

    // normalized 'a'
    #pragma unroll
    for (int t = tid; t < TT; t += NT)
        out[A_OFF + (size_t)b * TT + t] = alpha_v(arow, t, ub, sqb) * inv;

    // heads
    const float4* __restrict__ q4 = (const float4*)(query + (size_t)b * QD);
    float pu = 0.0f, ps = 0.0f;
    #pragma unroll
    for (int j = 0; j < 2; j++) {
        const int i = j * NT + tid;
        const float4 q  = q4[i];
        const float4 wq = ((const float4*)(W_u  + CD))[i];
        const float4 wz = ((const float4*)(W_sq + CD))[i];
        pu += q.x * wq.x + q.y * wq.y + q.z * wq.z + q.w * wq.w;
        ps += q.x * wz.x + q.y * wz.y + q.z * wz.z + q.w * wz.w;
    }
    #pragma unroll
    for (int o = 16; o > 0; o >>= 1) {
        pu += __shfl_xor_sync(0xffffffffu, pu, o);
        ps += __shfl_xor_sync(0xffffffffu, ps, o);
    }
    if ((tid & 31) == 0) { sm.fu[tid >> 5] = pu; sm.fs[tid >> 5] = ps; }
    __syncthreads();
    if (tid == 0) {
        float hu2 = 0.0f, hs2 = 0.0f;
        #pragma unroll
        for (int k = 0; k < SPLITS; k++) {
            hu2 += hdot[((size_t)b * SPLITS + k) * 2 + 0];
            hs2 += hdot[((size_t)b * SPLITS + k) * 2 + 1];
        }
        const float PU = hu2 * inv + (sm.fu[0] + sm.fu[1]) + (sm.fu[2] + sm.fu[3]) + b_u[0];
        const float PS = hs2 * inv + (sm.fs[0] + sm.fs[1]) + (sm.fs[2] + sm.fs[3]) + b_sq[0];
        out[U_OFF + b]  = 1.0f / (1.0f + expf(-PU));
        out[SQ_OFF + b] = 1.0f / (1.0f + expf(-PS)) + 1.0f;
    }
}

extern "C" void kernel_launch(void* const* d_in, const int* in_sizes, int n_in,
                              void* d_out, int out_size)
{
    const float* query  = (const float*)d_in[0];  // [B,1,QD]
    const float* inputs = (const float*)d_in[1];  // [B,T,CD]
    const float* alpha  = (const float*)d_in[2];  // [B,T]
    const float* u      = (const float*)d_in[3];  // [B,1]
    const float* sq     = (const float*)d_in[4];  // [B,1]
    const float* W_u    = (const float*)d_in[5];  // [QD+CD,1]
    const float* b_u    = (const float*)d_in[6];  // [1]
    const float* W_sq   = (const float*)d_in[7];  // [QD+CD,1]
    const float* b_sq   = (const float*)d_in[8];  // [1]
    float* out = (float*)d_out;

    float* partial; float* vsum; float* hdot; unsigned int* cnt;
    cudaGetSymbolAddress((void**)&partial, g_partial);
    cudaGetSymbolAddress((void**)&vsum, g_vsum);
    cudaGetSymbolAddress((void**)&hdot, g_hdot);
    cudaGetSymbolAddress((void**)&cnt, g_cnt);

    dim3 g(SPLITS, BB);
    k_all<<<g, NT>>>(inputs, alpha, u, sq, query,
                     W_u, b_u, W_sq, b_sq,
                     out, partial, vsum, hdot, cnt);
}

// round 14
// speedup vs baseline: 1.1511x; 1.1511x over previous
#include <cuda_runtime.h>
#include <cuda_bf16.h>
#include <math.h>

// Problem constants
#define BB 64
#define TT 1024
#define QD 1024
#define CD 512
#define NT 256          // threads per block
#define NCB 8           // column blocks per batch
#define CBW 64          // columns per block
#define NG  16          // float4 groups per slab (CBW/4)
#define NSL (NT / NG)   // t-slices per block = 16
#define SLT (TT / NSL)  // t per slice = 64

// Output layout (float32): context[B,CD] | a[B,T] | u_new[B] | sq_new[B]
#define CTX_OFF 0
#define A_OFF   (BB * CD)                 // 32768
#define U_OFF   (A_OFF + BB * TT)         // 98304
#define SQ_OFF  (U_OFF + BB)              // 98368

// Cross-block scratch
__device__ float        g_hdot[BB * NCB * 2];
__device__ unsigned int g_cnt[BB];           // zero-init; finalizer resets

__device__ __forceinline__ float alpha_v(
    const float* __restrict__ arow, int t, float ub, float sqb)
{
    const float cur  = arow[t];
    const float prev = (t > 0) ? arow[t - 1] : 0.0f;
    const float base = fmaf(-ub, cur, cur) + fmaf(ub, prev, 1e-6f);
    return __expf(sqb * __logf(base));   // base > 0 always
}

// ---------------------------------------------------------------------------
// Single kernel, col-split (R10 structure) + register double-buffered loads.
// Grid (NCB, B), NT threads. Each block owns 64 context columns over all t.
// Prologue loads 4 rows/thread BEFORE the MUFU alpha phase so DRAM stays busy
// while v[t] is computed; main loop prefetches 4 rows ahead in registers.
// Last-ticket block per batch finalizes the sigmoid heads.
// ---------------------------------------------------------------------------
__global__ void __launch_bounds__(NT) k_all(
    const float* __restrict__ inputs,
    const float* __restrict__ alpha,
    const float* __restrict__ u,
    const float* __restrict__ sq,
    const float* __restrict__ query,
    const float* __restrict__ W_u,  const float* __restrict__ b_u,
    const float* __restrict__ W_sq, const float* __restrict__ b_sq,
    float* __restrict__ out,
    float* __restrict__ hdot,
    unsigned int* __restrict__ cnt)
{
    const int cb  = blockIdx.x;
    const int b   = blockIdx.y;
    const int tid = threadIdx.x;
    const int lane = tid & 31;
    const int wid  = tid >> 5;

    __shared__ float  sa[TT];
    __shared__ float4 part[NSL * NG];
    __shared__ float  red[8];
    __shared__ float  hus[NG], hss[NG];
    __shared__ unsigned int tk;

    const int g  = tid & (NG - 1);
    const int sl = tid >> 4;                   // tid / NG
    const float4* __restrict__ inp =
        (const float4*)(inputs + ((size_t)b * TT + sl * SLT) * CD + cb * CBW) + g;
    #define RSTR (CD / 4)

    // --- prologue: 4 input rows in flight BEFORE the MUFU phase ---
    float4 c0 = __ldcs(&inp[0 * RSTR]);
    float4 c1 = __ldcs(&inp[1 * RSTR]);
    float4 c2 = __ldcs(&inp[2 * RSTR]);
    float4 c3 = __ldcs(&inp[3 * RSTR]);

    // --- v[t] (4 per thread) + S; overlaps the loads above ---
    const float ub  = u[b];
    const float sqb = sq[b];
    const float* arow = alpha + (size_t)b * TT;
    float sacc = 0.0f;
    #pragma unroll
    for (int k = 0; k < TT / NT; k++) {
        const int t = tid + k * NT;
        const float v = alpha_v(arow, t, ub, sqb);
        sa[t] = v;
        sacc += v;
    }
    #pragma unroll
    for (int o = 16; o > 0; o >>= 1) sacc += __shfl_xor_sync(0xffffffffu, sacc, o);
    if (lane == 0) red[wid] = sacc;
    __syncthreads();
    const float S = ((red[0] + red[1]) + (red[2] + red[3]))
                  + ((red[4] + red[5]) + (red[6] + red[7]));
    const float inv = 1.0f / S;

    if (cb == 0) {
        #pragma unroll
        for (int k = 0; k < TT / NT; k++) {
            const int t = tid + k * NT;
            out[A_OFF + (size_t)b * TT + t] = sa[t] * inv;
        }
    }

    // --- main loop: consume current 4 rows, prefetch next 4 (reg dbl-buf) ---
    const float* __restrict__ w = sa + sl * SLT;
    float4 ac0 = {0,0,0,0}, ac1 = {0,0,0,0}, ac2 = {0,0,0,0}, ac3 = {0,0,0,0};

    #pragma unroll
    for (int i = 0; i < SLT; i += 4) {
        float4 n0, n1, n2, n3;
        if (i + 4 < SLT) {                     // constant-folded under full unroll
            n0 = __ldcs(&inp[(size_t)(i + 4) * RSTR]);
            n1 = __ldcs(&inp[(size_t)(i + 5) * RSTR]);
            n2 = __ldcs(&inp[(size_t)(i + 6) * RSTR]);
            n3 = __ldcs(&inp[(size_t)(i + 7) * RSTR]);
        }
        const float w0 = w[i + 0], w1 = w[i + 1], w2 = w[i + 2], w3 = w[i + 3];
        ac0.x = fmaf(w0, c0.x, ac0.x); ac0.y = fmaf(w0, c0.y, ac0.y);
        ac0.z = fmaf(w0, c0.z, ac0.z); ac0.w = fmaf(w0, c0.w, ac0.w);
        ac1.x = fmaf(w1, c1.x, ac1.x); ac1.y = fmaf(w1, c1.y, ac1.y);
        ac1.z = fmaf(w1, c1.z, ac1.z); ac1.w = fmaf(w1, c1.w, ac1.w);
        ac2.x = fmaf(w2, c2.x, ac2.x); ac2.y = fmaf(w2, c2.y, ac2.y);
        ac2.z = fmaf(w2, c2.z, ac2.z); ac2.w = fmaf(w2, c2.w, ac2.w);
        ac3.x = fmaf(w3, c3.x, ac3.x); ac3.y = fmaf(w3, c3.y, ac3.y);
        ac3.z = fmaf(w3, c3.z, ac3.z); ac3.w = fmaf(w3, c3.w, ac3.w);
        if (i + 4 < SLT) { c0 = n0; c1 = n1; c2 = n2; c3 = n3; }
    }

    float4 acc;
    acc.x = (ac0.x + ac1.x) + (ac2.x + ac3.x);
    acc.y = (ac0.y + ac1.y) + (ac2.y + ac3.y);
    acc.z = (ac0.z + ac1.z) + (ac2.z + ac3.z);
    acc.w = (ac0.w + ac1.w) + (ac2.w + ac3.w);
    part[sl * NG + g] = acc;
    __syncthreads();

    // --- fold slices, write final normalized ctx columns ---
    if (tid < NG) {
        float4 c = {0,0,0,0};
        #pragma unroll
        for (int s = 0; s < NSL; s++) {
            const float4 p = part[s * NG + tid];
            c.x += p.x; c.y += p.y; c.z += p.z; c.w += p.w;
        }
        c.x *= inv; c.y *= inv; c.z *= inv; c.w *= inv;
        ((float4*)(out + CTX_OFF + (size_t)b * CD + cb * CBW))[tid] = c;

        const float4 wu = ((const float4*)(W_u  + cb * CBW))[tid];
        const float4 ws = ((const float4*)(W_sq + cb * CBW))[tid];
        hus[tid] = c.x * wu.x + c.y * wu.y + c.z * wu.z + c.w * wu.w;
        hss[tid] = c.x * ws.x + c.y * ws.y + c.z * ws.z + c.w * ws.w;
    }
    __syncthreads();

    // --- publish + ticket ---
    if (tid == 0) {
        float hu = 0.0f, hs = 0.0f;
        #pragma unroll
        for (int i = 0; i < NG; i++) { hu += hus[i]; hs += hss[i]; }
        hdot[((size_t)b * NCB + cb) * 2 + 0] = hu;
        hdot[((size_t)b * NCB + cb) * 2 + 1] = hs;
        unsigned int old;
        asm volatile("atom.add.acq_rel.gpu.global.u32 %0, [%1], %2;"
                     : "=r"(old) : "l"(cnt + b), "r"(1u) : "memory");
        tk = old;
    }
    __syncthreads();
    if (tk != NCB - 1) return;

    // ====================== tail: heads for batch b =========================
    if (tid == 0) cnt[b] = 0u;                // replay-safe reset

    const float4 q  = ((const float4*)(query + (size_t)b * QD))[tid];
    const float4 wq = ((const float4*)(W_u  + CD))[tid];
    const float4 wz = ((const float4*)(W_sq + CD))[tid];
    float pu = q.x * wq.x + q.y * wq.y + q.z * wq.z + q.w * wq.w;
    float ps = q.x * wz.x + q.y * wz.y + q.z * wz.z + q.w * wz.w;
    #pragma unroll
    for (int o = 16; o > 0; o >>= 1) {
        pu += __shfl_xor_sync(0xffffffffu, pu, o);
        ps += __shfl_xor_sync(0xffffffffu, ps, o);
    }
    __shared__ float ru2[8], rs2[8];
    if (lane == 0) { ru2[wid] = pu; rs2[wid] = ps; }
    __syncthreads();

    if (tid == 0) {
        float hu = 0.0f, hs = 0.0f;
        #pragma unroll
        for (int k = 0; k < NCB; k++) {
            hu += hdot[((size_t)b * NCB + k) * 2 + 0];
            hs += hdot[((size_t)b * NCB + k) * 2 + 1];
        }
        const float QU = ((ru2[0] + ru2[1]) + (ru2[2] + ru2[3]))
                       + ((ru2[4] + ru2[5]) + (ru2[6] + ru2[7]));
        const float QS = ((rs2[0] + rs2[1]) + (rs2[2] + rs2[3]))
                       + ((rs2[4] + rs2[5]) + (rs2[6] + rs2[7]));
        const float PU = hu + QU + b_u[0];
        const float PS = hs + QS + b_sq[0];
        out[U_OFF + b]  = 1.0f / (1.0f + expf(-PU));
        out[SQ_OFF + b] = 1.0f / (1.0f + expf(-PS)) + 1.0f;
    }
}

extern "C" void kernel_launch(void* const* d_in, const int* in_sizes, int n_in,
                              void* d_out, int out_size)
{
    const float* query  = (const float*)d_in[0];  // [B,1,QD]
    const float* inputs = (const float*)d_in[1];  // [B,T,CD]
    const float* alpha  = (const float*)d_in[2];  // [B,T]
    const float* u      = (const float*)d_in[3];  // [B,1]
    const float* sq     = (const float*)d_in[4];  // [B,1]
    const float* W_u    = (const float*)d_in[5];  // [QD+CD,1]
    const float* b_u    = (const float*)d_in[6];  // [1]
    const float* W_sq   = (const float*)d_in[7];  // [QD+CD,1]
    const float* b_sq   = (const float*)d_in[8];  // [1]
    float* out = (float*)d_out;

    float* hdot;
    unsigned int* cnt;
    cudaGetSymbolAddress((void**)&hdot, g_hdot);
    cudaGetSymbolAddress((void**)&cnt, g_cnt);

    dim3 g(NCB, BB);
    k_all<<<g, NT>>>(inputs, alpha, u, sq, query,
                     W_u, b_u, W_sq, b_sq, out, hdot, cnt);
}